// round 9
// baseline (speedup 1.0000x reference)
#include <cuda_runtime.h>
#include <cstdint>
#include <math.h>

#define N_PTS    65536
#define DIM      128
#define KCODES   1024
#define KC       64              // codes per smem tile
#define NTILES   (KCODES / KC)   // 16
#define CJ       4               // codes per thread per tile
#define RP       4               // row-pairs per thread
#define ROWS_CTA 128
#define PAIRS    64
#define THREADS  256
#define NCTAS    (N_PTS / ROWS_CTA)   // 512

typedef unsigned long long ull;

// ---- f32x2 packed math (sm_103a); lanes are IEEE fp32 fma.rn ----
__device__ __forceinline__ ull dup2(float a) {
    ull r; asm("mov.b64 %0, {%1, %1};" : "=l"(r) : "f"(a)); return r;
}
__device__ __forceinline__ void unpack2(ull v, float& a, float& b) {
    asm("mov.b64 {%0, %1}, %2;" : "=f"(a), "=f"(b) : "l"(v));
}
__device__ __forceinline__ ull fma2(ull a, ull b, ull c) {
    ull d; asm("fma.rn.f32x2 %0, %1, %2, %3;" : "=l"(d) : "l"(a), "l"(b), "l"(c)); return d;
}

// ---- device scratch ----
__device__ float g_bsq[KCODES];
__device__ int   g_counts[KCODES];
__device__ float g_bloss[NCTAS];

// smem layout (bytes)
#define SM_XS    0                     // ull  xs[128 k][64 pair]  = 65536
#define SM_CS    65536                 // f32  cs[KC][128 k]       = 32768
#define SM_BS    98304                 // f32  bs[KC]              = 256
#define SM_A     98560                 // f32  sA[128 rows]        = 512
#define SM_TOTAL 99072
// overlays on CS region, used only after the mainloop (barrier-separated):
#define SM_SD    SM_CS                 // f32 sd[16][128] = 8192
#define SM_SI    (SM_CS + 8192)        // int si[16][128] = 8192
#define SM_SIDX  (SM_CS + 16384)       // int sidx[128]   = 512
#define SM_RED   (SM_CS + 16896)       // f32 red[256]    = 1024

// ============================================================
// 1) B_k = fl( exact double sum of fl(c^2) ), staged + coalesced.
//    128 blocks x 128 threads; 8 codes per block.
// ============================================================
__global__ void prep_kernel(const float* __restrict__ cb) {
    __shared__ float sc[8][DIM];
    const int t = threadIdx.x;
    const int b = blockIdx.x;

    const float4* c4 = (const float4*)(cb + (size_t)b * 8 * DIM);
    #pragma unroll
    for (int i = 0; i < 2; i++) {                 // 256 float4 total
        int idx  = t + 128 * i;
        int row  = idx >> 5;
        int posq = idx & 31;
        float4 v = c4[idx];
        sc[row][posq * 4 + 0] = v.x;
        sc[row][posq * 4 + 1] = v.y;
        sc[row][posq * 4 + 2] = v.z;
        sc[row][posq * 4 + 3] = v.w;
    }
    __syncthreads();

    if (t < 8) {
        double s = 0.0;
        #pragma unroll 8
        for (int k = 0; k < DIM; k++) {
            float q = __fmul_rn(sc[t][k], sc[t][k]);
            s += (double)q;
        }
        g_bsq[b * 8 + t] = (float)s;
    }
    if (b < 8) g_counts[b * 128 + t] = 0;
}

// ============================================================
// 2) Main: 2 CTAs/SM, conflict-free LDS, register tile RP x CJ,
//    bit-faithful sequential fp32 chains, fused epilogue.
// ============================================================
__global__ __launch_bounds__(THREADS, 2)
void vq_main(const float* __restrict__ x, const float* __restrict__ cb,
             float* __restrict__ outq, float* __restrict__ oute) {
    extern __shared__ char smem[];
    ull*    xs   = (ull*)(smem + SM_XS);     // [k*64 + pair]; lane0=row pair, lane1=row pair+64
    float*  xsf  = (float*)(smem + SM_XS);   // scalar view
    float*  cs   = (float*)(smem + SM_CS);   // [code*128 + k]
    float4* cs4  = (float4*)(smem + SM_CS);
    float*  bs   = (float*)(smem + SM_BS);
    float*  sA   = (float*)(smem + SM_A);
    float*  sd   = (float*)(smem + SM_SD);
    int*    si   = (int*)(smem + SM_SI);
    int*    sidx = (int*)(smem + SM_SIDX);
    float*  red  = (float*)(smem + SM_RED);

    const int t    = threadIdx.x;
    const int pg   = t >> 4;      // 0..15  : pair group (uniform-ish per warp)
    const int cg   = t & 15;      // 0..15  : code group
    const int base = blockIdx.x * ROWS_CTA;

    // thread's 4 pairs
    int P[RP];
    P[0] = 2 * pg;      P[1] = 2 * pg + 1;
    P[2] = 2 * pg + 32; P[3] = 2 * pg + 33;

    // ---- stage x pair-packed: lane0 = row base+pr, lane1 = row base+64+pr
    {
        const float4* x4 = (const float4*)(x + (size_t)base * DIM);
        #pragma unroll
        for (int i = 0; i < (ROWS_CTA * DIM / 4) / THREADS; i++) {   // 16
            int idx  = t + THREADS * i;
            int row  = idx >> 5;
            int posq = idx & 31;
            float4 v = x4[idx];
            int pr = row & 63, ln = row >> 6, k0 = posq * 4;
            xsf[((k0 + 0) * PAIRS + pr) * 2 + ln] = v.x;
            xsf[((k0 + 1) * PAIRS + pr) * 2 + ln] = v.y;
            xsf[((k0 + 2) * PAIRS + pr) * 2 + ln] = v.z;
            xsf[((k0 + 3) * PAIRS + pr) * 2 + ln] = v.w;
        }
    }
    __syncthreads();

    // ---- A = compensated (Kahan) fp32 sum of fl(x^2), one thread per row.
    // Terms all-positive, no cancellation: result == correctly-rounded exact
    // sum (== the previously-passing double-exact A) except w.p. ~2^-25/row.
    if (t < ROWS_CTA) {
        const int pr = t & 63, ln = t >> 6;
        float s = 0.f, comp = 0.f;
        #pragma unroll 4
        for (int k = 0; k < DIM; k++) {
            float v  = xsf[(k * PAIRS + pr) * 2 + ln];
            float tm = __fmul_rn(v, v);
            float y  = __fsub_rn(tm, comp);
            float u  = __fadd_rn(s, y);
            comp     = __fsub_rn(__fsub_rn(u, s), y);
            s        = u;
        }
        sA[t] = s;
    }
    __syncthreads();

    float A0[RP], A1[RP];
    #pragma unroll
    for (int r = 0; r < RP; r++) { A0[r] = sA[P[r]]; A1[r] = sA[P[r] + 64]; }

    float best0[RP], best1[RP];
    int   bi0[RP],   bi1[RP];
    #pragma unroll
    for (int r = 0; r < RP; r++) {
        best0[r] = INFINITY; best1[r] = INFINITY; bi0[r] = 0; bi1[r] = 0;
    }

    const ull* xp0 = xs + 2 * pg;
    const ull* xp1 = xs + 2 * pg + 32;

    for (int kt = 0; kt < NTILES; kt++) {
        __syncthreads();
        {
            const float4* c4 = (const float4*)(cb + (size_t)kt * KC * DIM);
            float4* s4 = (float4*)cs;
            #pragma unroll
            for (int i = 0; i < (KC * DIM / 4) / THREADS; i++)       // 8
                s4[t + THREADS * i] = c4[t + THREADS * i];
            if (t < KC) bs[t] = g_bsq[kt * KC + t];
        }
        __syncthreads();

        ull acc[RP][CJ];
        #pragma unroll
        for (int r = 0; r < RP; r++)
            #pragma unroll
            for (int c = 0; c < CJ; c++) acc[r][c] = 0ull;

        const float4* cbase = cs4 + (cg * CJ) * (DIM / 4);

        #pragma unroll 1
        for (int k4 = 0; k4 < DIM / 4; k4++) {
            ull xv[4][RP];
            #pragma unroll
            for (int kk = 0; kk < 4; kk++) {
                const int ko = (4 * k4 + kk) * PAIRS;
                ulonglong2 a = *(const ulonglong2*)(xp0 + ko);   // pairs 2pg,2pg+1
                ulonglong2 b = *(const ulonglong2*)(xp1 + ko);   // pairs +32,+33
                xv[kk][0] = a.x; xv[kk][1] = a.y;
                xv[kk][2] = b.x; xv[kk][3] = b.y;
            }
            #pragma unroll
            for (int c = 0; c < CJ; c++) {
                float4 cv = cbase[c * (DIM / 4) + k4];
                ull d0 = dup2(cv.x), d1 = dup2(cv.y);
                ull d2 = dup2(cv.z), d3 = dup2(cv.w);
                // ascending k within each (r,c) chain
                #pragma unroll
                for (int r = 0; r < RP; r++) acc[r][c] = fma2(xv[0][r], d0, acc[r][c]);
                #pragma unroll
                for (int r = 0; r < RP; r++) acc[r][c] = fma2(xv[1][r], d1, acc[r][c]);
                #pragma unroll
                for (int r = 0; r < RP; r++) acc[r][c] = fma2(xv[2][r], d2, acc[r][c]);
                #pragma unroll
                for (int r = 0; r < RP; r++) acc[r][c] = fma2(xv[3][r], d3, acc[r][c]);
            }
        }

        // d = fl( fl(A + B) - 2*dot ) — reference's exact fp32 formula
        #pragma unroll
        for (int c = 0; c < CJ; c++) {
            float B    = bs[cg * CJ + c];
            int   gidx = kt * KC + cg * CJ + c;
            #pragma unroll
            for (int r = 0; r < RP; r++) {
                float f0, f1;
                unpack2(acc[r][c], f0, f1);
                float dd0 = __fadd_rn(__fadd_rn(A0[r], B), -(2.0f * f0));
                float dd1 = __fadd_rn(__fadd_rn(A1[r], B), -(2.0f * f1));
                if (dd0 < best0[r]) { best0[r] = dd0; bi0[r] = gidx; }
                if (dd1 < best1[r]) { best1[r] = dd1; bi1[r] = gidx; }
            }
        }
    }

    __syncthreads();   // mainloop done; safe to overlay cs region

    #pragma unroll
    for (int r = 0; r < RP; r++) {
        sd[cg * ROWS_CTA + P[r]]      = best0[r];
        si[cg * ROWS_CTA + P[r]]      = bi0[r];
        sd[cg * ROWS_CTA + P[r] + 64] = best1[r];
        si[cg * ROWS_CTA + P[r] + 64] = bi1[r];
    }
    __syncthreads();

    // lexicographic (d, idx) reduction over the 16 code groups
    if (t < ROWS_CTA) {
        float bd = sd[t];  int bi = si[t];
        #pragma unroll
        for (int g = 1; g < 16; g++) {
            float od = sd[g * ROWS_CTA + t]; int oi = si[g * ROWS_CTA + t];
            if (od < bd || (od == bd && oi < bi)) { bd = od; bi = oi; }
        }
        sidx[t] = bi;
        atomicAdd(&g_counts[bi], 1);
    }
    __syncthreads();

    // ---- quantized + loss: 2 threads per row (one half-row each)
    float lsum = 0.f;
    {
        const int row = t >> 1, half = t & 1;
        const int code = sidx[row];
        const int pr = row & 63, ln = row >> 6;
        const float4* q4 = (const float4*)(cb + (size_t)code * DIM + half * 64);
        float* qo = outq + (size_t)(base + row) * DIM + half * 64;  // 4B-aligned
        #pragma unroll 4
        for (int i = 0; i < 16; i++) {
            float4 q = q4[i];
            int k0 = half * 64 + 4 * i;
            float xa = xsf[((k0 + 0) * PAIRS + pr) * 2 + ln];
            float xb = xsf[((k0 + 1) * PAIRS + pr) * 2 + ln];
            float xc = xsf[((k0 + 2) * PAIRS + pr) * 2 + ln];
            float xd = xsf[((k0 + 3) * PAIRS + pr) * 2 + ln];
            float d0 = q.x - xa, d1 = q.y - xb, d2 = q.z - xc, d3 = q.w - xd;
            lsum += d0 * d0 + d1 * d1 + d2 * d2 + d3 * d3;
            qo[4 * i + 0] = q.x; qo[4 * i + 1] = q.y;
            qo[4 * i + 2] = q.z; qo[4 * i + 3] = q.w;
        }
    }

    __syncthreads();
    red[t] = lsum;
    __syncthreads();
    for (int s = 128; s > 0; s >>= 1) {
        if (t < s) red[t] += red[t + s];
        __syncthreads();
    }
    if (t == 0) g_bloss[blockIdx.x] = red[0];

    // ---- fused encodings: cooperative coalesced one-hot rows
    for (int r2 = 0; r2 < ROWS_CTA; r2++) {
        int idx = sidx[r2];
        float2* erow = (float2*)(oute + (size_t)(base + r2) * KCODES);
        int p2a = t,       pa = 2 * p2a;
        int p2b = t + 256, pb = 2 * p2b;
        float2 va, vb;
        va.x = (pa     == idx) ? 1.f : 0.f;
        va.y = (pa + 1 == idx) ? 1.f : 0.f;
        vb.x = (pb     == idx) ? 1.f : 0.f;
        vb.y = (pb + 1 == idx) ? 1.f : 0.f;
        erow[p2a] = va;
        erow[p2b] = vb;
    }
}

// ============================================================
// 3) Finalize: loss + perplexity scalars
// ============================================================
__global__ void fin_kernel(float* __restrict__ out_loss,
                           float* __restrict__ out_perp) {
    __shared__ float sh[1024];
    const int t = threadIdx.x;

    float c = (float)g_counts[t];
    float p = c * (1.0f / (float)N_PTS);
    sh[t] = p * logf(p + 1e-10f);
    __syncthreads();
    for (int s = 512; s > 0; s >>= 1) {
        if (t < s) sh[t] += sh[t + s];
        __syncthreads();
    }
    float ent = sh[0];
    __syncthreads();

    sh[t] = (t < NCTAS) ? g_bloss[t] : 0.f;
    __syncthreads();
    for (int s = 512; s > 0; s >>= 1) {
        if (t < s) sh[t] += sh[t + s];
        __syncthreads();
    }
    if (t == 0) {
        *out_perp = expf(-ent);
        *out_loss = 1.25f * sh[0] / (float)((size_t)N_PTS * DIM);
    }
}

// ============================================================
// launch
// ============================================================
extern "C" void kernel_launch(void* const* d_in, const int* in_sizes, int n_in,
                              void* d_out, int out_size) {
    const float* x  = (const float*)d_in[0];   // [65536, 128] f32
    const float* cb = (const float*)d_in[1];   // [1024, 128]  f32
    float* out  = (float*)d_out;
    float* outq = out + 1;
    float* outp = out + 1 + (size_t)N_PTS * DIM;
    float* oute = outp + 1;

    static int attr_done = 0;
    if (!attr_done) {
        cudaFuncSetAttribute(vq_main, cudaFuncAttributeMaxDynamicSharedMemorySize,
                             SM_TOTAL);
        attr_done = 1;
    }

    prep_kernel<<<KCODES / 8, 128>>>(cb);
    vq_main<<<NCTAS, THREADS, SM_TOTAL>>>(x, cb, outq, oute);
    fin_kernel<<<1, 1024>>>(out, outp);
}

// round 11
// speedup vs baseline: 2.2026x; 2.2026x over previous
#include <cuda_runtime.h>
#include <cstdint>
#include <math.h>

#define N_PTS    65536
#define DIM      128
#define KCODES   1024
#define KC       64              // codes per smem tile
#define NTILES   (KCODES / KC)   // 16
#define CJ       8               // codes per thread per tile (warp-uniform group)
#define RP       4               // row-pairs per thread
#define ROWS_CTA 256
#define PAIRS    128
#define THREADS  256
#define NCTAS    (N_PTS / ROWS_CTA)   // 256

typedef unsigned long long ull;

// ---- f32x2 packed math (sm_103a); lanes are IEEE fp32 fma.rn ----
__device__ __forceinline__ ull dup2(float a) {
    ull r; asm("mov.b64 %0, {%1, %1};" : "=l"(r) : "f"(a)); return r;
}
__device__ __forceinline__ void unpack2(ull v, float& a, float& b) {
    asm("mov.b64 {%0, %1}, %2;" : "=f"(a), "=f"(b) : "l"(v));
}
__device__ __forceinline__ ull fma2(ull a, ull b, ull c) {
    ull d; asm("fma.rn.f32x2 %0, %1, %2, %3;" : "=l"(d) : "l"(a), "l"(b), "l"(c)); return d;
}

// ---- device scratch ----
__device__ float g_bsq[KCODES];
__device__ int   g_counts[KCODES];
__device__ float g_bloss[NCTAS];

// smem layout (bytes)
#define SM_XS    0                      // ull  xs[128 k][128 pair] = 131072
#define SM_CS    131072                 // ull  csd[KC][128 k] dup'd = 65536
#define SM_BS    196608                 // f32  bs[KC]               = 256
#define SM_A     196864                 // f32  sA[256 rows]         = 1024
#define SM_TOTAL 197888
// overlays on CS region, used only after the mainloop (barrier-separated):
#define SM_SD    SM_CS                  // f32 sd[8][256]  = 8192
#define SM_SI    (SM_CS + 8192)         // int si[8][256]  = 8192
#define SM_SIDX  (SM_CS + 16384)        // int sidx[256]   = 1024
#define SM_RED   (SM_CS + 17408)        // f32 red[256]    = 1024

// ============================================================
// 1) B_k = fl( double-accumulated sum of fl(c^2) ), coalesced staging
// ============================================================
__global__ void prep_kernel(const float* __restrict__ cb) {
    __shared__ float sc[8][DIM];
    const int t = threadIdx.x;
    const int b = blockIdx.x;

    const float4* c4 = (const float4*)(cb + (size_t)b * 8 * DIM);
    #pragma unroll
    for (int i = 0; i < 2; i++) {
        int idx  = t + 128 * i;
        int row  = idx >> 5;
        int posq = idx & 31;
        float4 v = c4[idx];
        sc[row][posq * 4 + 0] = v.x;
        sc[row][posq * 4 + 1] = v.y;
        sc[row][posq * 4 + 2] = v.z;
        sc[row][posq * 4 + 3] = v.w;
    }
    __syncthreads();

    if (t < 8) {
        double s = 0.0;
        #pragma unroll 8
        for (int k = 0; k < DIM; k++) {
            float q = __fmul_rn(sc[t][k], sc[t][k]);
            s += (double)q;
        }
        g_bsq[b * 8 + t] = (float)s;
    }
    if (b < 8) g_counts[b * 128 + t] = 0;
}

// ============================================================
// 2) Main: warp-uniform code groups (broadcast LDS), vector x loads,
//    pre-duplicated codes, bit-faithful sequential fp32 chains.
// ============================================================
__global__ __launch_bounds__(THREADS)
void vq_main(const float* __restrict__ x, const float* __restrict__ cb,
             float* __restrict__ outq, float* __restrict__ oute) {
    extern __shared__ char smem[];
    ull*    xs   = (ull*)(smem + SM_XS);     // [k*128 + pair]; lanes = rows (p, p+128)
    float*  xsf  = (float*)(smem + SM_XS);   // scalar view
    ull*    csd  = (ull*)(smem + SM_CS);     // [code*128 + k], (c,c) duplicated
    float*  bs   = (float*)(smem + SM_BS);
    float*  sA   = (float*)(smem + SM_A);
    float*  sd   = (float*)(smem + SM_SD);
    int*    si   = (int*)(smem + SM_SI);
    int*    sidx = (int*)(smem + SM_SIDX);
    float*  red  = (float*)(smem + SM_RED);

    const int t    = threadIdx.x;
    const int pg   = t & 31;      // lane: pair group
    const int cg   = t >> 5;      // warp-uniform: code group (codes cg*8..cg*8+7)
    const int base = blockIdx.x * ROWS_CTA;

    // thread's 4 pairs: two vector-adjacent duos
    int P[RP];
    P[0] = 2 * pg;      P[1] = 2 * pg + 1;
    P[2] = 2 * pg + 64; P[3] = 2 * pg + 65;

    // ---- stage x pair-packed: lane0 = row base+pr, lane1 = row base+128+pr
    {
        const float4* x4 = (const float4*)(x + (size_t)base * DIM);
        #pragma unroll
        for (int i = 0; i < (ROWS_CTA * DIM / 4) / THREADS; i++) {   // 32
            int idx  = t + THREADS * i;
            int row  = idx >> 5;
            int posq = idx & 31;
            float4 v = x4[idx];
            int pr = row & 127, ln = row >> 7, k0 = posq * 4;
            xsf[((k0 + 0) * PAIRS + pr) * 2 + ln] = v.x;
            xsf[((k0 + 1) * PAIRS + pr) * 2 + ln] = v.y;
            xsf[((k0 + 2) * PAIRS + pr) * 2 + ln] = v.z;
            xsf[((k0 + 3) * PAIRS + pr) * 2 + ln] = v.w;
        }
    }
    __syncthreads();

    // ---- A = Kahan fp32 sum of fl(x^2), one thread per row (validated R9)
    {
        const int pr = t & 127, ln = t >> 7;
        float s = 0.f, comp = 0.f;
        #pragma unroll 4
        for (int k = 0; k < DIM; k++) {
            float v  = xsf[(k * PAIRS + pr) * 2 + ln];
            float tm = __fmul_rn(v, v);
            float y  = __fsub_rn(tm, comp);
            float u  = __fadd_rn(s, y);
            comp     = __fsub_rn(__fsub_rn(u, s), y);
            s        = u;
        }
        sA[t] = s;
    }
    __syncthreads();

    float A0[RP], A1[RP];
    #pragma unroll
    for (int r = 0; r < RP; r++) { A0[r] = sA[P[r]]; A1[r] = sA[P[r] + 128]; }

    float best0[RP], best1[RP];
    int   bi0[RP],   bi1[RP];
    #pragma unroll
    for (int r = 0; r < RP; r++) {
        best0[r] = INFINITY; best1[r] = INFINITY; bi0[r] = 0; bi1[r] = 0;
    }

    for (int kt = 0; kt < NTILES; kt++) {
        __syncthreads();
        // stage KC codes duplicated (c,c): csd[code][k]
        {
            const float4* c4 = (const float4*)(cb + (size_t)kt * KC * DIM);
            #pragma unroll
            for (int i = 0; i < (KC * DIM / 4) / THREADS; i++) {     // 8
                int idx  = t + THREADS * i;
                int code = idx >> 5;
                int posq = idx & 31;
                float4 v = c4[idx];
                ulonglong2* dst = (ulonglong2*)(csd + code * DIM + posq * 4);
                ulonglong2 w0, w1;
                w0.x = dup2(v.x); w0.y = dup2(v.y);
                w1.x = dup2(v.z); w1.y = dup2(v.w);
                dst[0] = w0; dst[1] = w1;
            }
            if (t < KC) bs[t] = g_bsq[kt * KC + t];
        }
        __syncthreads();

        ull acc[RP][CJ];
        #pragma unroll
        for (int r = 0; r < RP; r++)
            #pragma unroll
            for (int c = 0; c < CJ; c++) acc[r][c] = 0ull;

        const ull* cdup = csd + (cg * CJ) * DIM;   // warp-uniform base

        #pragma unroll 2
        for (int kk = 0; kk < DIM / 2; kk++) {
            const ull* xr0 = xs + (2 * kk) * PAIRS + 2 * pg;
            ulonglong2 a0 = *(const ulonglong2*)(xr0);          // k=2kk,   pairs 2pg,2pg+1
            ulonglong2 a1 = *(const ulonglong2*)(xr0 + 64);     // k=2kk,   pairs +64,+65
            ulonglong2 b0 = *(const ulonglong2*)(xr0 + PAIRS);  // k=2kk+1
            ulonglong2 b1 = *(const ulonglong2*)(xr0 + PAIRS + 64);
            #pragma unroll
            for (int c = 0; c < CJ; c++) {
                ulonglong2 cc = *(const ulonglong2*)(cdup + c * DIM + 2 * kk);
                // ascending k per (r,c) chain: k=2kk then k=2kk+1
                acc[0][c] = fma2(a0.x, cc.x, acc[0][c]);
                acc[1][c] = fma2(a0.y, cc.x, acc[1][c]);
                acc[2][c] = fma2(a1.x, cc.x, acc[2][c]);
                acc[3][c] = fma2(a1.y, cc.x, acc[3][c]);
                acc[0][c] = fma2(b0.x, cc.y, acc[0][c]);
                acc[1][c] = fma2(b0.y, cc.y, acc[1][c]);
                acc[2][c] = fma2(b1.x, cc.y, acc[2][c]);
                acc[3][c] = fma2(b1.y, cc.y, acc[3][c]);
            }
        }

        // d = fl( fl(A + B) - 2*dot ) — reference's exact fp32 formula
        #pragma unroll
        for (int c = 0; c < CJ; c++) {
            float B    = bs[cg * CJ + c];
            int   gidx = kt * KC + cg * CJ + c;
            #pragma unroll
            for (int r = 0; r < RP; r++) {
                float f0, f1;
                unpack2(acc[r][c], f0, f1);
                float dd0 = __fadd_rn(__fadd_rn(A0[r], B), -(2.0f * f0));
                float dd1 = __fadd_rn(__fadd_rn(A1[r], B), -(2.0f * f1));
                if (dd0 < best0[r]) { best0[r] = dd0; bi0[r] = gidx; }
                if (dd1 < best1[r]) { best1[r] = dd1; bi1[r] = gidx; }
            }
        }
    }

    __syncthreads();   // mainloop done; safe to overlay cs region

    #pragma unroll
    for (int r = 0; r < RP; r++) {
        sd[cg * ROWS_CTA + P[r]]       = best0[r];
        si[cg * ROWS_CTA + P[r]]       = bi0[r];
        sd[cg * ROWS_CTA + P[r] + 128] = best1[r];
        si[cg * ROWS_CTA + P[r] + 128] = bi1[r];
    }
    __syncthreads();

    // lexicographic (d, idx) reduction over the 8 code groups; 1 row/thread
    {
        float bd = sd[t];  int bi = si[t];
        #pragma unroll
        for (int g = 1; g < 8; g++) {
            float od = sd[g * ROWS_CTA + t]; int oi = si[g * ROWS_CTA + t];
            if (od < bd || (od == bd && oi < bi)) { bd = od; bi = oi; }
        }
        sidx[t] = bi;
        atomicAdd(&g_counts[bi], 1);
    }
    __syncthreads();

    // ---- quantized + loss: one row per thread
    float lsum = 0.f;
    {
        const int code = sidx[t];
        const int pr = t & 127, ln = t >> 7;
        const float4* q4 = (const float4*)(cb + (size_t)code * DIM);
        float* qo = outq + (size_t)(base + t) * DIM;   // 4B-aligned only
        #pragma unroll 4
        for (int i = 0; i < DIM / 4; i++) {
            float4 q = q4[i];
            float xa = xsf[((4 * i + 0) * PAIRS + pr) * 2 + ln];
            float xb = xsf[((4 * i + 1) * PAIRS + pr) * 2 + ln];
            float xc = xsf[((4 * i + 2) * PAIRS + pr) * 2 + ln];
            float xd = xsf[((4 * i + 3) * PAIRS + pr) * 2 + ln];
            float d0 = q.x - xa, d1 = q.y - xb, d2 = q.z - xc, d3 = q.w - xd;
            lsum += d0 * d0 + d1 * d1 + d2 * d2 + d3 * d3;
            qo[4 * i + 0] = q.x; qo[4 * i + 1] = q.y;
            qo[4 * i + 2] = q.z; qo[4 * i + 3] = q.w;
        }
    }

    __syncthreads();
    red[t] = lsum;
    __syncthreads();
    for (int s = 128; s > 0; s >>= 1) {
        if (t < s) red[t] += red[t + s];
        __syncthreads();
    }
    if (t == 0) g_bloss[blockIdx.x] = red[0];

    // ---- fused encodings: cooperative coalesced one-hot rows
    for (int r2 = 0; r2 < ROWS_CTA; r2++) {
        int idx = sidx[r2];
        float2* erow = (float2*)(oute + (size_t)(base + r2) * KCODES);
        int p2a = t,       pa = 2 * p2a;
        int p2b = t + 256, pb = 2 * p2b;
        float2 va, vb;
        va.x = (pa     == idx) ? 1.f : 0.f;
        va.y = (pa + 1 == idx) ? 1.f : 0.f;
        vb.x = (pb     == idx) ? 1.f : 0.f;
        vb.y = (pb + 1 == idx) ? 1.f : 0.f;
        erow[p2a] = va;
        erow[p2b] = vb;
    }
}

// ============================================================
// 3) Finalize: loss + perplexity scalars
// ============================================================
__global__ void fin_kernel(float* __restrict__ out_loss,
                           float* __restrict__ out_perp) {
    __shared__ float sh[1024];
    const int t = threadIdx.x;

    float c = (float)g_counts[t];
    float p = c * (1.0f / (float)N_PTS);
    sh[t] = p * logf(p + 1e-10f);
    __syncthreads();
    for (int s = 512; s > 0; s >>= 1) {
        if (t < s) sh[t] += sh[t + s];
        __syncthreads();
    }
    float ent = sh[0];
    __syncthreads();

    sh[t] = (t < NCTAS) ? g_bloss[t] : 0.f;
    __syncthreads();
    for (int s = 512; s > 0; s >>= 1) {
        if (t < s) sh[t] += sh[t + s];
        __syncthreads();
    }
    if (t == 0) {
        *out_perp = expf(-ent);
        *out_loss = 1.25f * sh[0] / (float)((size_t)N_PTS * DIM);
    }
}

// ============================================================
// launch
// ============================================================
extern "C" void kernel_launch(void* const* d_in, const int* in_sizes, int n_in,
                              void* d_out, int out_size) {
    const float* x  = (const float*)d_in[0];   // [65536, 128] f32
    const float* cb = (const float*)d_in[1];   // [1024, 128]  f32
    float* out  = (float*)d_out;
    float* outq = out + 1;
    float* outp = out + 1 + (size_t)N_PTS * DIM;
    float* oute = outp + 1;

    static int attr_done = 0;
    if (!attr_done) {
        cudaFuncSetAttribute(vq_main, cudaFuncAttributeMaxDynamicSharedMemorySize,
                             SM_TOTAL);
        attr_done = 1;
    }

    prep_kernel<<<KCODES / 8, 128>>>(cb);
    vq_main<<<NCTAS, THREADS, SM_TOTAL>>>(x, cb, outq, oute);
    fin_kernel<<<1, 1024>>>(out, outp);
}